// round 5
// baseline (speedup 1.0000x reference)
#include <cuda_runtime.h>
#include <cuda_bf16.h>
#include <math_constants.h>

// Scratch (allocation-free rule): segment starts + per-chunk partial maxima.
#define MAX_SEG   (1 << 16)
#define CHUNKS    4
__device__ int   g_starts[MAX_SEG];
__device__ float g_partial[8192 * 128];   // 4 MB: (n_seg*CHUNKS) x D partials

// ---------------------------------------------------------------------------
// Exclusive prefix-sum of int32 sizes -> g_starts (single block, shfl scan).
// ---------------------------------------------------------------------------
__global__ void scan_sizes_kernel(const int* __restrict__ sizes, int n) {
    __shared__ int warp_tot[32];
    const int t = threadIdx.x, lane = t & 31, wid = t >> 5;
    int offset = 0;
    for (int base = 0; base < n; base += 2048) {
        const int i0 = base + 2 * t, i1 = i0 + 1;
        const int a0 = (i0 < n) ? sizes[i0] : 0;
        const int a1 = (i1 < n) ? sizes[i1] : 0;
        const int v = a0 + a1;
        // Inclusive warp scan of pair-sums.
        int s = v;
        #pragma unroll
        for (int d = 1; d < 32; d <<= 1) {
            const int u = __shfl_up_sync(0xFFFFFFFFu, s, d);
            if (lane >= d) s += u;
        }
        if (lane == 31) warp_tot[wid] = s;
        __syncthreads();
        if (wid == 0) {
            int wv = warp_tot[lane];
            #pragma unroll
            for (int d = 1; d < 32; d <<= 1) {
                const int u = __shfl_up_sync(0xFFFFFFFFu, wv, d);
                if (lane >= d) wv += u;
            }
            warp_tot[lane] = wv;
        }
        __syncthreads();
        const int warp_off = (wid > 0) ? warp_tot[wid - 1] : 0;
        const int excl = s + warp_off - v;   // exclusive pair-scan value
        if (i0 < n) g_starts[i0] = offset + excl;
        if (i1 < n) g_starts[i1] = offset + excl + a0;
        const int tile_tot = warp_tot[31];
        __syncthreads();                     // protect warp_tot for next tile
        offset += tile_tot;
    }
}

__device__ __forceinline__ float4 fmax4(float4 a, float4 b) {
    a.x = fmaxf(a.x, b.x);
    a.y = fmaxf(a.y, b.y);
    a.z = fmaxf(a.z, b.z);
    a.w = fmaxf(a.w, b.w);
    return a;
}

// ---------------------------------------------------------------------------
// Phase A: one CTA per (segment, quarter-chunk). 256 thr = 8 rowgroups x 32
// float4-cols. Each warp-iteration loads one coalesced 512B row; unroll x4.
// ---------------------------------------------------------------------------
__global__ void __launch_bounds__(256, 8)
partial_max_kernel(const float* __restrict__ x,
                   const int* __restrict__ sizes,
                   const int* __restrict__ wptr) {
    const int chunk = blockIdx.x;
    const int seg   = chunk >> 2;
    const int c     = chunk & 3;

    const int start = g_starts[seg];
    const int m     = sizes[seg] - *wptr + 1;       // rows to reduce
    const int m4    = (m + CHUNKS - 1) >> 2;        // rows per chunk
    const int lo    = c * m4;
    const int hi    = min(lo + m4, m);

    const int tid  = threadIdx.x;
    const int c4   = tid & 31;
    const int rgrp = tid >> 5;

    const float4* __restrict__ base =
        reinterpret_cast<const float4*>(x) + (size_t)start * 32;

    float4 acc = make_float4(-CUDART_INF_F, -CUDART_INF_F,
                             -CUDART_INF_F, -CUDART_INF_F);

    int r = lo + rgrp;
    for (; r + 24 < hi; r += 32) {
        const float4 v0 = base[(r      ) * 32 + c4];
        const float4 v1 = base[(r +  8) * 32 + c4];
        const float4 v2 = base[(r + 16) * 32 + c4];
        const float4 v3 = base[(r + 24) * 32 + c4];
        acc = fmax4(acc, fmax4(fmax4(v0, v1), fmax4(v2, v3)));
    }
    for (; r < hi; r += 8) {
        acc = fmax4(acc, base[r * 32 + c4]);
    }

    __shared__ float4 sm[256];
    sm[tid] = acc;
    __syncthreads();
    if (tid < 128) sm[tid] = fmax4(sm[tid], sm[tid + 128]);
    __syncthreads();
    if (tid < 64)  sm[tid] = fmax4(sm[tid], sm[tid + 64]);
    __syncthreads();
    if (tid < 32) {
        const float4 res = fmax4(sm[tid], sm[tid + 32]);
        reinterpret_cast<float4*>(g_partial)[chunk * 32 + c4] = res;
    }
}

// ---------------------------------------------------------------------------
// Phase B: reduce the 4 chunk-partials per segment into out.
// One thread per (segment, float4-column).
// ---------------------------------------------------------------------------
__global__ void __launch_bounds__(256)
combine_kernel(float* __restrict__ out, int n_seg) {
    const int idx = blockIdx.x * 256 + threadIdx.x;   // seg*32 + c4
    if (idx >= n_seg * 32) return;
    const int seg = idx >> 5;
    const int c4  = idx & 31;
    const float4* p = reinterpret_cast<const float4*>(g_partial);
    float4 a = p[(seg * 4 + 0) * 32 + c4];
    a = fmax4(a, p[(seg * 4 + 1) * 32 + c4]);
    a = fmax4(a, p[(seg * 4 + 2) * 32 + c4]);
    a = fmax4(a, p[(seg * 4 + 3) * 32 + c4]);
    reinterpret_cast<float4*>(out)[idx] = a;
}

extern "C" void kernel_launch(void* const* d_in, const int* in_sizes, int n_in,
                              void* d_out, int out_size) {
    const float* x     = (const float*)d_in[0];
    const int*   sizes = (const int*)d_in[1];
    const int*   wptr  = (const int*)d_in[2];
    float*       out   = (float*)d_out;

    const int n_seg = in_sizes[1];

    scan_sizes_kernel<<<1, 1024>>>(sizes, n_seg);
    partial_max_kernel<<<n_seg * CHUNKS, 256>>>(x, sizes, wptr);
    combine_kernel<<<(n_seg * 32 + 255) / 256, 256>>>(out, n_seg);
}

// round 9
// speedup vs baseline: 1.1533x; 1.1533x over previous
#include <cuda_runtime.h>
#include <cuda_bf16.h>
#include <math_constants.h>

__device__ __forceinline__ float4 fmax4(float4 a, float4 b) {
    a.x = fmaxf(a.x, b.x);
    a.y = fmaxf(a.y, b.y);
    a.z = fmaxf(a.z, b.z);
    a.w = fmaxf(a.w, b.w);
    return a;
}

// One CTA per segment, 128 threads = 4 row-groups x 32 float4-columns (D=128).
// occ=16 -> 64 warps/SM -> all 2048 CTAs resident in ONE wave (no quantization).
// Segment start computed inline (L2-hot reads of the small sizes array).
__global__ void __launch_bounds__(128, 16)
seg_prefix_max_kernel(const float* __restrict__ x,
                      const int* __restrict__ sizes,
                      const int* __restrict__ wptr,
                      float* __restrict__ out) {
    const int seg  = blockIdx.x;
    const int tid  = threadIdx.x;
    const int lane = tid & 31;
    const int wid  = tid >> 5;

    // ---- Inline exclusive-prefix: start = sum(sizes[0..seg)) ----
    int psum = 0;
    for (int i = tid; i < seg; i += 128) psum += sizes[i];
    #pragma unroll
    for (int d = 16; d > 0; d >>= 1)
        psum += __shfl_down_sync(0xFFFFFFFFu, psum, d);
    __shared__ int ssum[4];
    if (lane == 0) ssum[wid] = psum;
    __syncthreads();
    const int start = ssum[0] + ssum[1] + ssum[2] + ssum[3];

    const int m = sizes[seg] - wptr[0] + 1;  // rows to reduce

    const int c4   = tid & 31;   // float4 column 0..31
    const int rgrp = tid >> 5;   // row group 0..3

    const float4* __restrict__ base =
        reinterpret_cast<const float4*>(x) + (size_t)start * 32;

    float4 acc = make_float4(-CUDART_INF_F, -CUDART_INF_F,
                             -CUDART_INF_F, -CUDART_INF_F);

    // 4 independent rows in flight per thread (coalesced 512B per warp-row).
    int r = rgrp;
    for (; r + 12 < m; r += 16) {
        const float4 v0 = base[(r     ) * 32 + c4];
        const float4 v1 = base[(r +  4) * 32 + c4];
        const float4 v2 = base[(r +  8) * 32 + c4];
        const float4 v3 = base[(r + 12) * 32 + c4];
        acc = fmax4(acc, fmax4(fmax4(v0, v1), fmax4(v2, v3)));
    }
    for (; r < m; r += 4) {
        acc = fmax4(acc, base[r * 32 + c4]);
    }

    // Reduce 4 row-groups -> 1 via shared memory.
    __shared__ float4 sm[128];
    sm[tid] = acc;
    __syncthreads();
    if (tid < 64) sm[tid] = fmax4(sm[tid], sm[tid + 64]);
    __syncthreads();
    if (tid < 32) {
        const float4 res = fmax4(sm[tid], sm[tid + 32]);
        reinterpret_cast<float4*>(out)[seg * 32 + c4] = res;
    }
}

extern "C" void kernel_launch(void* const* d_in, const int* in_sizes, int n_in,
                              void* d_out, int out_size) {
    const float* x     = (const float*)d_in[0];
    const int*   sizes = (const int*)d_in[1];
    const int*   wptr  = (const int*)d_in[2];
    float*       out   = (float*)d_out;

    const int n_seg = in_sizes[1];

    seg_prefix_max_kernel<<<n_seg, 128>>>(x, sizes, wptr, out);
}